// round 1
// baseline (speedup 1.0000x reference)
#include <cuda_runtime.h>
#include <math.h>

#define D_DIM 1024
#define F_DIM 4096
#define E_DIM 8
#define NTOK  16384           // B*S = 4*4096
#define NCH   64              // chunks over F
#define ROWS_PER_CH (F_DIM/NCH)

// ---------------- device scratch (no allocations allowed) ----------------
__device__ __align__(16) float g_part[NCH][5][D_DIM];   // partial F-sums
__device__ __align__(16) float g_mw[E_DIM][D_DIM];      // mu_w[e][d]
__device__ __align__(16) float g_vw[E_DIM][D_DIM];      // var_w[e][d]
__device__ float g_bias_mean;

typedef unsigned long long u64;

__device__ __forceinline__ u64 fma2(u64 a, u64 b, u64 c) {
    u64 d;
    asm("fma.rn.f32x2 %0, %1, %2, %3;" : "=l"(d) : "l"(a), "l"(b), "l"(c));
    return d;
}
__device__ __forceinline__ u64 mul2(u64 a, u64 b) {
    u64 d;
    asm("mul.rn.f32x2 %0, %1, %2;" : "=l"(d) : "l"(a), "l"(b));
    return d;
}
__device__ __forceinline__ float f2lo(u64 v) { return __uint_as_float((unsigned)v); }
__device__ __forceinline__ float f2hi(u64 v) { return __uint_as_float((unsigned)(v >> 32)); }

// ---------------- kernel A: column stats of W_base / W_delta -------------
// grid (D/256, NCH), block 256. Coalesced column reductions, 5 moments.
__global__ void k_reduceW(const float* __restrict__ Wb, const float* __restrict__ Wd) {
    int d  = blockIdx.x * blockDim.x + threadIdx.x;
    int f0 = blockIdx.y * ROWS_PER_CH;
    const float* pb = Wb + (size_t)f0 * D_DIM + d;
    const float* pd = Wd + (size_t)f0 * D_DIM + d;
    float sb = 0.f, sd = 0.f, sbb = 0.f, sbd = 0.f, sdd = 0.f;
#pragma unroll 8
    for (int i = 0; i < ROWS_PER_CH; i++) {
        float b = __ldg(pb + (size_t)i * D_DIM);
        float w = __ldg(pd + (size_t)i * D_DIM);
        sb += b; sd += w;
        sbb = fmaf(b, b, sbb);
        sdd = fmaf(w, w, sdd);
        sbd = fmaf(b, w, sbd);
    }
    g_part[blockIdx.y][0][d] = sb;
    g_part[blockIdx.y][1][d] = sd;
    g_part[blockIdx.y][2][d] = sbb;
    g_part[blockIdx.y][3][d] = sbd;
    g_part[blockIdx.y][4][d] = sdd;
}

// ---------------- kernel B: finalize mu_w / var_w, bias mean -------------
__global__ void k_finalize(const float* __restrict__ alpha,
                           const float* __restrict__ beta,
                           const float* __restrict__ bias) {
    int d = blockIdx.x * blockDim.x + threadIdx.x;
    float sb = 0.f, sd = 0.f, sbb = 0.f, sbd = 0.f, sdd = 0.f;
#pragma unroll 4
    for (int c = 0; c < NCH; c++) {
        sb  += g_part[c][0][d];
        sd  += g_part[c][1][d];
        sbb += g_part[c][2][d];
        sbd += g_part[c][3][d];
        sdd += g_part[c][4][d];
    }
    const float inv = 1.0f / (float)F_DIM;
    float mb = sb * inv, md = sd * inv;
    float ebb = sbb * inv, ebd = sbd * inv, edd = sdd * inv;
#pragma unroll
    for (int e = 0; e < E_DIM; e++) {
        float a = __ldg(&alpha[e]);
        float b = __ldg(&beta[e]);
        float m = a * mb + b * md;
        float v = a * a * ebb + 2.0f * a * b * ebd + b * b * edd - m * m;
        g_mw[e][d] = m;
        g_vw[e][d] = v;
    }
    if (blockIdx.x == 0) {
        __shared__ float sh[256];
        float s = 0.f;
        for (int i = threadIdx.x; i < F_DIM; i += 256) s += bias[i];
        sh[threadIdx.x] = s;
        __syncthreads();
        for (int o = 128; o > 0; o >>= 1) {
            if (threadIdx.x < o) sh[threadIdx.x] += sh[threadIdx.x + o];
            __syncthreads();
        }
        if (threadIdx.x == 0) g_bias_mean = sh[0] * inv;
    }
}

// ---------------- kernel C: fused router ---------------------------------
// One warp handles 4 tokens (R=4) to amortize mw/vw L1 reloads.
// f32x2 packed FMAs halve the FFMA instruction count.
__global__ void __launch_bounds__(128) k_router(const float* __restrict__ x,
                                                float* __restrict__ out) {
    const int lane  = threadIdx.x & 31;
    const int wid   = threadIdx.x >> 5;
    const int warpg = blockIdx.x * 4 + wid;       // 0..4095
    const int tok0  = warpg * 4;                  // 4 tokens per warp
    const float* xp = x + (size_t)tok0 * D_DIM;

    u64 am[4][E_DIM];
    u64 av[4][E_DIM];
#pragma unroll
    for (int t = 0; t < 4; t++) {
#pragma unroll
        for (int e = 0; e < E_DIM; e++) { am[t][e] = 0ull; av[t][e] = 0ull; }
    }

#pragma unroll
    for (int c = 0; c < 8; c++) {
        const int off = c * 128 + lane * 4;
        ulonglong2 xv[4], xs[4];
#pragma unroll
        for (int t = 0; t < 4; t++)
            xv[t] = *reinterpret_cast<const ulonglong2*>(xp + (size_t)t * D_DIM + off);
#pragma unroll
        for (int t = 0; t < 4; t++) {
            xs[t].x = mul2(xv[t].x, xv[t].x);
            xs[t].y = mul2(xv[t].y, xv[t].y);
        }
#pragma unroll
        for (int e = 0; e < E_DIM; e++) {
            ulonglong2 m = *reinterpret_cast<const ulonglong2*>(&g_mw[e][off]);
            ulonglong2 v = *reinterpret_cast<const ulonglong2*>(&g_vw[e][off]);
#pragma unroll
            for (int t = 0; t < 4; t++) {
                am[t][e] = fma2(xv[t].x, m.x, am[t][e]);
                am[t][e] = fma2(xv[t].y, m.y, am[t][e]);
                av[t][e] = fma2(xs[t].x, v.x, av[t][e]);
                av[t][e] = fma2(xs[t].y, v.y, av[t][e]);
            }
        }
    }

    // Warp reduction -> shared staging (one distinct lane per (t,e) pair)
    __shared__ float smu[4][4][E_DIM];
    __shared__ float sva[4][4][E_DIM];
#pragma unroll
    for (int t = 0; t < 4; t++) {
#pragma unroll
        for (int e = 0; e < E_DIM; e++) {
            float m = f2lo(am[t][e]) + f2hi(am[t][e]);
            float v = f2lo(av[t][e]) + f2hi(av[t][e]);
#pragma unroll
            for (int o = 16; o > 0; o >>= 1) {
                m += __shfl_xor_sync(0xffffffffu, m, o);
                v += __shfl_xor_sync(0xffffffffu, v, o);
            }
            if (lane == t * E_DIM + e) {    // t*8+e in [0,32): unique lane
                smu[wid][t][e] = m;
                sva[wid][t][e] = v;
            }
        }
    }
    __syncthreads();

    // Epilogue: thread per token (16 tokens per block)
    if (threadIdx.x < 16) {
        const int w = threadIdx.x >> 2;
        const int t = threadIdx.x & 3;
        const int tok = blockIdx.x * 16 + threadIdx.x;
        const float bm = g_bias_mean;

        float l[E_DIM];
#pragma unroll
        for (int e = 0; e < E_DIM; e++) {
            float mu = smu[w][t][e] + bm;
            float s  = sva[w][t][e] + 1e-8f;
            float z  = mu * rsqrtf(s) * 0.70710678118654752f;
            l[e] = erff(z);
        }

        // top-2 (ties: lower index first, matching lax.top_k)
        int i1 = -1, i2 = -1;
        float v1 = -2.0f, v2 = -2.0f;   // erf range is [-1,1]
#pragma unroll
        for (int e = 0; e < E_DIM; e++) {
            float val = l[e];
            if (val > v1)      { v2 = v1; i2 = i1; v1 = val; i1 = e; }
            else if (val > v2) { v2 = val; i2 = e; }
        }
        float w2 = 1.0f / (1.0f + expf(v1 - v2));
        float w1 = 1.0f - w2;

        float wv[E_DIM];
#pragma unroll
        for (int e = 0; e < E_DIM; e++)
            wv[e] = (e == i1) ? w1 : ((e == i2) ? w2 : 0.0f);

        float4* ow = reinterpret_cast<float4*>(out + (size_t)tok * E_DIM);
        ow[0] = make_float4(wv[0], wv[1], wv[2], wv[3]);
        ow[1] = make_float4(wv[4], wv[5], wv[6], wv[7]);
        float4* ol = reinterpret_cast<float4*>(out + (size_t)NTOK * E_DIM + (size_t)tok * E_DIM);
        ol[0] = make_float4(l[0], l[1], l[2], l[3]);
        ol[1] = make_float4(l[4], l[5], l[6], l[7]);
    }
}

// ---------------- launch ---------------------------------------------------
extern "C" void kernel_launch(void* const* d_in, const int* in_sizes, int n_in,
                              void* d_out, int out_size) {
    const float* x     = (const float*)d_in[0];
    const float* Wb    = (const float*)d_in[1];
    const float* Wd    = (const float*)d_in[2];
    const float* bias  = (const float*)d_in[3];
    const float* alpha = (const float*)d_in[4];
    const float* beta  = (const float*)d_in[5];
    float* out = (float*)d_out;

    k_reduceW<<<dim3(D_DIM / 256, NCH), 256>>>(Wb, Wd);
    k_finalize<<<D_DIM / 256, 256>>>(alpha, beta, bias);
    k_router<<<NTOK / 16, 128>>>(x, out);
}

// round 2
// speedup vs baseline: 1.3003x; 1.3003x over previous
#include <cuda_runtime.h>
#include <math.h>

#define D_DIM 1024
#define F_DIM 4096
#define E_DIM 8
#define NTOK  16384           // B*S = 4*4096
#define NCH   128             // chunks over F for kernel A
#define ROWS_PER_CH (F_DIM/NCH)   // 32
#define NG    8               // groups for stage-1 reduce
#define CH_PER_G (NCH/NG)     // 16

// ---------------- device scratch ----------------
__device__ __align__(16) float g_part [NCH][5][D_DIM];
__device__ __align__(16) float g_part2[NG ][5][D_DIM];
__device__ __align__(16) float g_stats[5][D_DIM];   // mb, md, cbb, cbd, cdd
__device__ float g_bias_mean;

typedef unsigned long long u64;

__device__ __forceinline__ u64 fma2(u64 a, u64 b, u64 c) {
    u64 d;
    asm("fma.rn.f32x2 %0, %1, %2, %3;" : "=l"(d) : "l"(a), "l"(b), "l"(c));
    return d;
}
__device__ __forceinline__ u64 mul2(u64 a, u64 b) {
    u64 d;
    asm("mul.rn.f32x2 %0, %1, %2;" : "=l"(d) : "l"(a), "l"(b));
    return d;
}
__device__ __forceinline__ float f2lo(u64 v) { return __uint_as_float((unsigned)v); }
__device__ __forceinline__ float f2hi(u64 v) { return __uint_as_float((unsigned)(v >> 32)); }

__device__ __forceinline__ void acc4(float4& s, float4 v)            { s.x += v.x; s.y += v.y; s.z += v.z; s.w += v.w; }
__device__ __forceinline__ void fma4(float4& s, float4 a, float4 b)  { s.x = fmaf(a.x,b.x,s.x); s.y = fmaf(a.y,b.y,s.y); s.z = fmaf(a.z,b.z,s.z); s.w = fmaf(a.w,b.w,s.w); }

// ---------------- kernel A: column stats of W_base / W_delta -------------
// grid NCH, block 256 (thread = one float4 column group). float4 loads, deep MLP.
__global__ void __launch_bounds__(256) k_reduceW(const float* __restrict__ Wb,
                                                 const float* __restrict__ Wd) {
    const int q = threadIdx.x;                    // 0..255 (float4 column)
    const float4* pb = reinterpret_cast<const float4*>(Wb) + (size_t)blockIdx.x * ROWS_PER_CH * 256 + q;
    const float4* pd = reinterpret_cast<const float4*>(Wd) + (size_t)blockIdx.x * ROWS_PER_CH * 256 + q;
    float4 sb = {0,0,0,0}, sd = {0,0,0,0}, sbb = {0,0,0,0}, sbd = {0,0,0,0}, sdd = {0,0,0,0};
#pragma unroll 8
    for (int i = 0; i < ROWS_PER_CH; i++) {
        float4 b = pb[(size_t)i * 256];
        float4 w = pd[(size_t)i * 256];
        acc4(sb, b); acc4(sd, w);
        fma4(sbb, b, b); fma4(sbd, b, w); fma4(sdd, w, w);
    }
    const int c = blockIdx.x;
    *reinterpret_cast<float4*>(&g_part[c][0][q*4]) = sb;
    *reinterpret_cast<float4*>(&g_part[c][1][q*4]) = sd;
    *reinterpret_cast<float4*>(&g_part[c][2][q*4]) = sbb;
    *reinterpret_cast<float4*>(&g_part[c][3][q*4]) = sbd;
    *reinterpret_cast<float4*>(&g_part[c][4][q*4]) = sdd;
}

// ---------------- kernel B1: first-stage chunk reduce ---------------------
// grid (4, NG), block 256
__global__ void k_reduce1(void) {
    const int d = blockIdx.x * 256 + threadIdx.x;
    const int g = blockIdx.y;
    float s0=0.f, s1=0.f, s2=0.f, s3=0.f, s4=0.f;
#pragma unroll
    for (int c = g * CH_PER_G; c < (g + 1) * CH_PER_G; c++) {
        s0 += g_part[c][0][d];
        s1 += g_part[c][1][d];
        s2 += g_part[c][2][d];
        s3 += g_part[c][3][d];
        s4 += g_part[c][4][d];
    }
    g_part2[g][0][d] = s0;
    g_part2[g][1][d] = s1;
    g_part2[g][2][d] = s2;
    g_part2[g][3][d] = s3;
    g_part2[g][4][d] = s4;
}

// ---------------- kernel B2: finalize centered stats + bias mean ----------
// grid 4, block 256
__global__ void k_finalize(const float* __restrict__ bias) {
    const int d = blockIdx.x * 256 + threadIdx.x;
    float s0=0.f, s1=0.f, s2=0.f, s3=0.f, s4=0.f;
#pragma unroll
    for (int g = 0; g < NG; g++) {
        s0 += g_part2[g][0][d];
        s1 += g_part2[g][1][d];
        s2 += g_part2[g][2][d];
        s3 += g_part2[g][3][d];
        s4 += g_part2[g][4][d];
    }
    const float inv = 1.0f / (float)F_DIM;
    float mb  = s0 * inv, md  = s1 * inv;
    float ebb = s2 * inv, ebd = s3 * inv, edd = s4 * inv;
    g_stats[0][d] = mb;
    g_stats[1][d] = md;
    g_stats[2][d] = ebb - mb * mb;     // cbb
    g_stats[3][d] = ebd - mb * md;     // cbd
    g_stats[4][d] = edd - md * md;     // cdd

    if (blockIdx.x == 0) {
        __shared__ float sh[256];
        float s = 0.f;
        for (int i = threadIdx.x; i < F_DIM; i += 256) s += bias[i];
        sh[threadIdx.x] = s;
        __syncthreads();
        for (int o = 128; o > 0; o >>= 1) {
            if (threadIdx.x < o) sh[threadIdx.x] += sh[threadIdx.x + o];
            __syncthreads();
        }
        if (threadIdx.x == 0) g_bias_mean = sh[0] * inv;
    }
}

// ---------------- kernel C: fused router (5-dot formulation) --------------
// warp handles 4 tokens; only 5 weight vectors (20KB total, L1-resident).
__global__ void __launch_bounds__(128) k_router(const float* __restrict__ x,
                                                const float* __restrict__ alpha,
                                                const float* __restrict__ beta,
                                                float* __restrict__ out) {
    const int lane = threadIdx.x & 31;
    const int wid  = threadIdx.x >> 5;
    const int tok0 = (blockIdx.x * 4 + wid) * 4;
    const float* xp = x + (size_t)tok0 * D_DIM;

    u64 acc[4][5];
#pragma unroll
    for (int t = 0; t < 4; t++)
#pragma unroll
        for (int s = 0; s < 5; s++) acc[t][s] = 0ull;

#pragma unroll
    for (int c = 0; c < 8; c++) {
        const int off = c * 128 + lane * 4;
        ulonglong2 sv0 = *reinterpret_cast<const ulonglong2*>(&g_stats[0][off]);
        ulonglong2 sv1 = *reinterpret_cast<const ulonglong2*>(&g_stats[1][off]);
        ulonglong2 sv2 = *reinterpret_cast<const ulonglong2*>(&g_stats[2][off]);
        ulonglong2 sv3 = *reinterpret_cast<const ulonglong2*>(&g_stats[3][off]);
        ulonglong2 sv4 = *reinterpret_cast<const ulonglong2*>(&g_stats[4][off]);
#pragma unroll
        for (int t = 0; t < 4; t++) {
            ulonglong2 xv = *reinterpret_cast<const ulonglong2*>(xp + (size_t)t * D_DIM + off);
            u64 xs0 = mul2(xv.x, xv.x);
            u64 xs1 = mul2(xv.y, xv.y);
            acc[t][0] = fma2(xv.x, sv0.x, acc[t][0]);
            acc[t][0] = fma2(xv.y, sv0.y, acc[t][0]);
            acc[t][1] = fma2(xv.x, sv1.x, acc[t][1]);
            acc[t][1] = fma2(xv.y, sv1.y, acc[t][1]);
            acc[t][2] = fma2(xs0,  sv2.x, acc[t][2]);
            acc[t][2] = fma2(xs1,  sv2.y, acc[t][2]);
            acc[t][3] = fma2(xs0,  sv3.x, acc[t][3]);
            acc[t][3] = fma2(xs1,  sv3.y, acc[t][3]);
            acc[t][4] = fma2(xs0,  sv4.x, acc[t][4]);
            acc[t][4] = fma2(xs1,  sv4.y, acc[t][4]);
        }
    }

    __shared__ float sred[4][4][5];
#pragma unroll
    for (int t = 0; t < 4; t++) {
#pragma unroll
        for (int s = 0; s < 5; s++) {
            float v = f2lo(acc[t][s]) + f2hi(acc[t][s]);
#pragma unroll
            for (int o = 16; o > 0; o >>= 1)
                v += __shfl_xor_sync(0xffffffffu, v, o);
            if (lane == t * 5 + s) sred[wid][t][s] = v;
        }
    }
    __syncthreads();

    // Epilogue: one thread per token (16 tokens per block)
    if (threadIdx.x < 16) {
        const int w = threadIdx.x >> 2;
        const int t = threadIdx.x & 3;
        const int tok = blockIdx.x * 16 + threadIdx.x;
        const float bm = g_bias_mean;

        const float d_mb = sred[w][t][0];
        const float d_md = sred[w][t][1];
        const float d_bb = sred[w][t][2];
        const float d_bd = sred[w][t][3];
        const float d_dd = sred[w][t][4];

        float l[E_DIM];
#pragma unroll
        for (int e = 0; e < E_DIM; e++) {
            float a = __ldg(&alpha[e]);
            float b = __ldg(&beta[e]);
            float mu = a * d_mb + b * d_md + bm;
            float va = a * a * d_bb + 2.0f * a * b * d_bd + b * b * d_dd;
            float z  = mu * rsqrtf(va + 1e-8f) * 0.70710678118654752f;
            l[e] = erff(z);
        }

        // top-2 (strict >, ties keep lower index first — matches lax.top_k)
        int i1 = -1, i2 = -1;
        float v1 = -2.0f, v2 = -2.0f;
#pragma unroll
        for (int e = 0; e < E_DIM; e++) {
            float val = l[e];
            if (val > v1)      { v2 = v1; i2 = i1; v1 = val; i1 = e; }
            else if (val > v2) { v2 = val; i2 = e; }
        }
        float w2 = 1.0f / (1.0f + expf(v1 - v2));
        float w1 = 1.0f - w2;

        float wv[E_DIM];
#pragma unroll
        for (int e = 0; e < E_DIM; e++)
            wv[e] = (e == i1) ? w1 : ((e == i2) ? w2 : 0.0f);

        float4* ow = reinterpret_cast<float4*>(out + (size_t)tok * E_DIM);
        ow[0] = make_float4(wv[0], wv[1], wv[2], wv[3]);
        ow[1] = make_float4(wv[4], wv[5], wv[6], wv[7]);
        float4* ol = reinterpret_cast<float4*>(out + (size_t)NTOK * E_DIM + (size_t)tok * E_DIM);
        ol[0] = make_float4(l[0], l[1], l[2], l[3]);
        ol[1] = make_float4(l[4], l[5], l[6], l[7]);
    }
}

// ---------------- launch ---------------------------------------------------
extern "C" void kernel_launch(void* const* d_in, const int* in_sizes, int n_in,
                              void* d_out, int out_size) {
    const float* x     = (const float*)d_in[0];
    const float* Wb    = (const float*)d_in[1];
    const float* Wd    = (const float*)d_in[2];
    const float* bias  = (const float*)d_in[3];
    const float* alpha = (const float*)d_in[4];
    const float* beta  = (const float*)d_in[5];
    float* out = (float*)d_out;

    k_reduceW<<<NCH, 256>>>(Wb, Wd);
    k_reduce1<<<dim3(D_DIM / 256, NG), 256>>>();
    k_finalize<<<D_DIM / 256, 256>>>(bias);
    k_router<<<NTOK / 16, 128>>>(x, alpha, beta, out);
}